// round 4
// baseline (speedup 1.0000x reference)
#include <cuda_runtime.h>
#include <cstdint>

#define BB 4
#define TT 2048
#define DD 512
#define HH 8
#define DK 64
#define BHN (BB*HH)          // 32
#define MROWS (BB*TT)        // 8192

// ---------------- scratch ----------------
__device__ unsigned long long g_qb[BHN*TT];
__device__ unsigned long long g_kb[BHN*TT];
__device__ unsigned long long g_vb[BHN*TT];
__device__ unsigned long long g_vT[BHN*DK*(TT/64)];   // [bh][d][w] bits over 64 k
__device__ unsigned char      g_xs[BB*TT*DD];         // scrambled X bytes

// ---------------- helpers ----------------
__device__ __forceinline__ unsigned long long pk2(float lo, float hi) {
    unsigned long long r;
    asm("mov.b64 %0, {%1,%2};" : "=l"(r) : "f"(lo), "f"(hi));
    return r;
}
__device__ __forceinline__ void unpk2(unsigned long long v, float& lo, float& hi) {
    asm("mov.b64 {%0,%1}, %2;" : "=f"(lo), "=f"(hi) : "l"(v));
}
__device__ __forceinline__ void fma2(unsigned long long& d, unsigned long long a,
                                     unsigned long long b) {
    asm("fma.rn.f32x2 %0, %1, %2, %0;" : "+l"(d) : "l"(a), "l"(b));
}
__device__ __forceinline__ unsigned expand4(unsigned x) {   // 4 bits -> 4 bytes
    return (x * 0x00204081u) & 0x01010101u;
}
__device__ __forceinline__ void mma_s8(int* c, unsigned a0, unsigned a1, unsigned a2,
                                       unsigned a3, unsigned b0, unsigned b1) {
    asm volatile(
        "mma.sync.aligned.m16n8k32.row.col.s32.s8.s8.s32 "
        "{%0,%1,%2,%3}, {%4,%5,%6,%7}, {%8,%9}, {%0,%1,%2,%3};"
        : "+r"(c[0]), "+r"(c[1]), "+r"(c[2]), "+r"(c[3])
        : "r"(a0), "r"(a1), "r"(a2), "r"(a3), "r"(b0), "r"(b1));
}

// local index maps for the 128x128 tile, per-thread 8m x 8n
// m: (mi<4) ? ty*4+mi : 64+ty*4+mi-4 ; n-pair base: (p<2) ? tx*4+2p : 64+tx*4+2p-4
__device__ __forceinline__ int mloc_of(int ty, int mi) {
    return (mi < 4) ? (ty * 4 + mi) : (64 + ty * 4 + (mi - 4));
}
__device__ __forceinline__ int nloc_of(int tx, int p) {
    return (p < 2) ? (tx * 4 + 2 * p) : (64 + tx * 4 + 2 * (p - 2));
}

// =====================================================================
// Fused q/k/v projection + spike + bitpack.
// A stored DUPLICATED in smem as f32x2 pairs (u64) -> inner loop is
// 6x LDS.128 + 32x FFMA2 per kk, no MOVs. FMA order per output unchanged.
// =====================================================================
__global__ __launch_bounds__(256, 2) void qkv_proj_kernel(
    const float* __restrict__ Aq, const float* __restrict__ Ak,
    const float* __restrict__ Av,
    const float* __restrict__ Wq, const float* __restrict__ Wk,
    const float* __restrict__ Wv,
    const float* __restrict__ bq, const float* __restrict__ bk,
    const float* __restrict__ bv, int DIN)
{
    __shared__ unsigned long long Ad[16][130];   // [k][m] duplicated pairs (pad 2)
    __shared__ float Wsh[16][128];               // [k][n]
    __shared__ unsigned char sbyte[128][128];

    const int tid = threadIdx.x;
    const int tx = tid & 15, ty = tid >> 4;

    int idx = blockIdx.x;
    int which, m0, n0, K;
    const float *A, *W, *bias;
    if (idx < 512) {
        which = 1 + (idx & 1);
        int s = idx >> 1;
        m0 = (s >> 2) << 7; n0 = (s & 3) << 7; K = DD;
    } else {
        which = 0;
        int s = idx - 512;
        m0 = (s >> 2) << 7; n0 = (s & 3) << 7; K = DIN;
    }
    A    = (which == 0) ? Aq : (which == 1) ? Ak : Av;
    W    = (which == 0) ? Wq : (which == 1) ? Wk : Wv;
    bias = (which == 0) ? bq : (which == 1) ? bk : bv;

    unsigned long long acc[8][4];
#pragma unroll
    for (int i = 0; i < 8; i++)
#pragma unroll
        for (int p = 0; p < 4; p++) acc[i][p] = 0ull;

    const int amm = tid >> 1, akoff = (tid & 1) * 8;
    const int wkk = tid >> 4, wnoff = (tid & 15) * 8;

    for (int k0 = 0; k0 < K; k0 += 16) {
        // ---- A tile -> Ad[k][m] (duplicated pairs) ----
        if (K == DD) {
            const float4* ap = (const float4*)(A + (size_t)(m0 + amm) * DD + k0 + akoff);
            float4 v0 = ap[0], v1 = ap[1];
            Ad[akoff + 0][amm] = pk2(v0.x, v0.x);
            Ad[akoff + 1][amm] = pk2(v0.y, v0.y);
            Ad[akoff + 2][amm] = pk2(v0.z, v0.z);
            Ad[akoff + 3][amm] = pk2(v0.w, v0.w);
            Ad[akoff + 4][amm] = pk2(v1.x, v1.x);
            Ad[akoff + 5][amm] = pk2(v1.y, v1.y);
            Ad[akoff + 6][amm] = pk2(v1.z, v1.z);
            Ad[akoff + 7][amm] = pk2(v1.w, v1.w);
        } else {
#pragma unroll
            for (int j = 0; j < 8; j++) {
                int kk = k0 + akoff + j;
                float v = (kk < K) ? A[(size_t)(m0 + amm) * K + kk] : 0.f;
                Ad[akoff + j][amm] = pk2(v, v);
            }
        }
        // ---- W tile -> Wsh[k][n] ----
        if (k0 + wkk < K) {
            const float4* wp = (const float4*)(W + (size_t)(k0 + wkk) * DD + n0 + wnoff);
            float4 w0 = wp[0], w1 = wp[1];
            *(float4*)&Wsh[wkk][wnoff] = w0;
            *(float4*)&Wsh[wkk][wnoff + 4] = w1;
        } else {
            float4 z = {0.f, 0.f, 0.f, 0.f};
            *(float4*)&Wsh[wkk][wnoff] = z;
            *(float4*)&Wsh[wkk][wnoff + 4] = z;
        }
        __syncthreads();
#pragma unroll
        for (int kk = 0; kk < 16; ++kk) {
            ulonglong2 a01 = *(const ulonglong2*)&Ad[kk][ty * 4];
            ulonglong2 a23 = *(const ulonglong2*)&Ad[kk][ty * 4 + 2];
            ulonglong2 a45 = *(const ulonglong2*)&Ad[kk][64 + ty * 4];
            ulonglong2 a67 = *(const ulonglong2*)&Ad[kk][64 + ty * 4 + 2];
            ulonglong2 w01 = *(const ulonglong2*)&Wsh[kk][tx * 4];
            ulonglong2 w23 = *(const ulonglong2*)&Wsh[kk][64 + tx * 4];
            unsigned long long am[8] = {a01.x, a01.y, a23.x, a23.y,
                                        a45.x, a45.y, a67.x, a67.y};
            unsigned long long wn[4] = {w01.x, w01.y, w23.x, w23.y};
#pragma unroll
            for (int mi = 0; mi < 8; mi++)
#pragma unroll
                for (int p = 0; p < 4; p++) fma2(acc[mi][p], am[mi], wn[p]);
        }
        __syncthreads();
    }

    // ---- spike -> bytes in smem ----
#pragma unroll
    for (int p = 0; p < 4; p++) {
        int nl = nloc_of(tx, p);
        float2 bl = *(const float2*)&bias[n0 + nl];
#pragma unroll
        for (int mi = 0; mi < 8; mi++) {
            float lo, hi; unpk2(acc[mi][p], lo, hi);
            uchar2 r;
            r.x = (lo + bl.x >= 1.0f) ? 1 : 0;
            r.y = (hi + bl.y >= 1.0f) ? 1 : 0;
            *(uchar2*)&sbyte[mloc_of(ty, mi)][nl] = r;
        }
    }
    __syncthreads();

    // ---- repack 64 bytes -> one uint64 per (row, head-half) ----
    {
        int row = tid >> 1, hf = tid & 1;
        unsigned long long bits = 0ull;
#pragma unroll
        for (int q = 0; q < 8; q++) {
            unsigned long long u = *(const unsigned long long*)&sbyte[row][hf * 64 + 8 * q];
#pragma unroll
            for (int j = 0; j < 8; j++)
                bits |= ((u >> (8 * j)) & 1ull) << (8 * q + j);
        }
        int m = m0 + row;
        int b = m >> 11, t = m & 2047;
        int head = (n0 >> 6) + hf;
        unsigned long long* dst = (which == 0) ? g_qb : (which == 1) ? g_kb : g_vb;
        dst[(size_t)((b << 3) + head) * TT + t] = bits;
    }
}

// ---------------- v bit transpose ----------------
__global__ void vtrans_kernel()
{
    int bx = blockIdx.x;
    int bh = bx >> 5, w = bx & 31;
    int tid = threadIdx.x;
    int lane = tid & 31, warp = tid >> 5;
    __shared__ unsigned sh[64][2];
    unsigned long long r = g_vb[(size_t)bh * TT + w * 64 + tid];
#pragma unroll 8
    for (int d = 0; d < 64; d++) {
        unsigned b = __ballot_sync(0xffffffffu, (unsigned)((r >> d) & 1ull));
        if (lane == 0) sh[d][warp] = b;
    }
    __syncthreads();
    g_vT[(size_t)(bh * 64 + tid) * 32 + w] =
        (unsigned long long)sh[tid][0] | ((unsigned long long)sh[tid][1] << 32);
}

// =====================================================================
// Attention: QK popcount -> s8 cnt tile -> PV via IMMA (exact).
// =====================================================================
__global__ __launch_bounds__(128) void attn_kernel(const float* __restrict__ scale_p)
{
    const int tid = threadIdx.x;
    const int lane = tid & 31;
    const int warpid = tid >> 5;
    const int g = lane >> 2, tg = lane & 3;
    const int rowA = warpid * 16 + g;

    int bx = blockIdx.x;
    int bh = bx & 31;
    int tq = 31 - (bx >> 5);          // big tiles first

    __shared__ unsigned long long qsh[64];
    __shared__ unsigned long long ksh[64];
    __shared__ unsigned char csh[64 * 68];

    const float scale = *scale_p;
    const size_t base = (size_t)bh * TT;

    if (tid < 64) qsh[tid] = g_qb[base + (size_t)tq * 64 + tid];

    int acc[8][4];
#pragma unroll
    for (int nt = 0; nt < 8; nt++)
#pragma unroll
        for (int r = 0; r < 4; r++) acc[nt][r] = 0;

    const int tQ = tid >> 1;
    const int khalf = tid & 1;

    for (int w = 0; w <= tq; ++w) {
        __syncthreads();
        if (tid < 64) ksh[tid] = g_kb[base + (size_t)w * 64 + tid];
        unsigned long long vt[8];
#pragma unroll
        for (int nt = 0; nt < 8; ++nt)
            vt[nt] = g_vT[((size_t)bh * 64 + nt * 8 + g) * 32 + w];
        __syncthreads();

        {
            unsigned long long q = qsh[tQ];
            const bool diag = (w == tq);
#pragma unroll 2
            for (int k4 = 0; k4 < 32; k4 += 4) {
                unsigned pack = 0;
#pragma unroll
                for (int j = 0; j < 4; ++j) {
                    int kc = khalf * 32 + k4 + j;
                    int c = __popcll(q & ksh[kc]);
                    if (diag && kc > tQ) c = 0;
                    pack |= (unsigned)c << (8 * j);
                }
                *(unsigned*)&csh[tQ * 68 + khalf * 32 + k4] = pack;
            }
        }
        __syncthreads();

#pragma unroll
        for (int s = 0; s < 2; ++s) {
            unsigned a0 = *(const unsigned*)&csh[rowA * 68 + s * 32 + tg * 4];
            unsigned a1 = *(const unsigned*)&csh[(rowA + 8) * 68 + s * 32 + tg * 4];
            unsigned a2 = *(const unsigned*)&csh[rowA * 68 + s * 32 + 16 + tg * 4];
            unsigned a3 = *(const unsigned*)&csh[(rowA + 8) * 68 + s * 32 + 16 + tg * 4];
#pragma unroll
            for (int nt = 0; nt < 8; ++nt) {
                unsigned b0 = expand4((unsigned)(vt[nt] >> (s * 32 + tg * 4)) & 0xFu);
                unsigned b1 = expand4((unsigned)(vt[nt] >> (s * 32 + 16 + tg * 4)) & 0xFu);
                mma_s8(acc[nt], a0, a1, a2, a3, b0, b1);
            }
        }
    }

    __syncthreads();
#pragma unroll
    for (int nt = 0; nt < 8; ++nt) {
        int d0 = nt * 8 + tg * 2;
        csh[d0 * 68 + rowA]           = ((float)acc[nt][0] * scale >= 1.0f) ? 1 : 0;
        csh[(d0 + 1) * 68 + rowA]     = ((float)acc[nt][1] * scale >= 1.0f) ? 1 : 0;
        csh[d0 * 68 + rowA + 8]       = ((float)acc[nt][2] * scale >= 1.0f) ? 1 : 0;
        csh[(d0 + 1) * 68 + rowA + 8] = ((float)acc[nt][3] * scale >= 1.0f) ? 1 : 0;
    }
    __syncthreads();
    {
        int d = tid >> 1, hf = tid & 1;
        size_t b = (size_t)(bh >> 3), h = (size_t)(bh & 7);
        size_t off = (b << 20) + (h << 17) + ((size_t)d << 11)
                   + (size_t)tq * 64 + (size_t)hf * 32;
#pragma unroll
        for (int q4 = 0; q4 < 32; q4 += 4) {
            unsigned v = *(const unsigned*)&csh[d * 68 + hf * 32 + q4];
            *(unsigned*)(g_xs + off + q4) = v;
        }
    }
}

// =====================================================================
// Output projection: binary A (bytes) expanded+duplicated into smem.
// =====================================================================
__global__ __launch_bounds__(256, 2) void out_proj_kernel(
    const float* __restrict__ W, const float* __restrict__ bias,
    float* __restrict__ out)
{
    __shared__ unsigned long long Ad[16][130];
    __shared__ float Wsh[16][128];

    const int tid = threadIdx.x;
    const int tx = tid & 15, ty = tid >> 4;
    const int m0 = blockIdx.y * 128, n0 = blockIdx.x * 128;

    unsigned long long acc[8][4];
#pragma unroll
    for (int i = 0; i < 8; i++)
#pragma unroll
        for (int p = 0; p < 4; p++) acc[i][p] = 0ull;

    const int amm = tid >> 1, akoff = (tid & 1) * 8;
    const int wkk = tid >> 4, wnoff = (tid & 15) * 8;

    for (int k0 = 0; k0 < DD; k0 += 16) {
        unsigned long long xu =
            *(const unsigned long long*)(g_xs + (size_t)(m0 + amm) * DD + k0 + akoff);
#pragma unroll
        for (int j = 0; j < 8; j++) {
            float v = (float)(int)((xu >> (8 * j)) & 1ull);
            Ad[akoff + j][amm] = pk2(v, v);
        }
        {
            const float4* wp = (const float4*)(W + (size_t)(k0 + wkk) * DD + n0 + wnoff);
            float4 w0 = wp[0], w1 = wp[1];
            *(float4*)&Wsh[wkk][wnoff] = w0;
            *(float4*)&Wsh[wkk][wnoff + 4] = w1;
        }
        __syncthreads();
#pragma unroll
        for (int kk = 0; kk < 16; ++kk) {
            ulonglong2 a01 = *(const ulonglong2*)&Ad[kk][ty * 4];
            ulonglong2 a23 = *(const ulonglong2*)&Ad[kk][ty * 4 + 2];
            ulonglong2 a45 = *(const ulonglong2*)&Ad[kk][64 + ty * 4];
            ulonglong2 a67 = *(const ulonglong2*)&Ad[kk][64 + ty * 4 + 2];
            ulonglong2 w01 = *(const ulonglong2*)&Wsh[kk][tx * 4];
            ulonglong2 w23 = *(const ulonglong2*)&Wsh[kk][64 + tx * 4];
            unsigned long long am[8] = {a01.x, a01.y, a23.x, a23.y,
                                        a45.x, a45.y, a67.x, a67.y};
            unsigned long long wn[4] = {w01.x, w01.y, w23.x, w23.y};
#pragma unroll
            for (int mi = 0; mi < 8; mi++)
#pragma unroll
                for (int p = 0; p < 4; p++) fma2(acc[mi][p], am[mi], wn[p]);
        }
        __syncthreads();
    }

    // ---- spike + vectorized store: two float4 per mi ----
#pragma unroll
    for (int mi = 0; mi < 8; mi++) {
        int m = m0 + mloc_of(ty, mi);
#pragma unroll
        for (int ph = 0; ph < 2; ph++) {         // ph=0 -> p{0,1}, ph=1 -> p{2,3}
            int nl = (ph == 0) ? (tx * 4) : (64 + tx * 4);
            float4 bl = *(const float4*)&bias[n0 + nl];
            float l0, h0, l1, h1;
            unpk2(acc[mi][2 * ph],     l0, h0);
            unpk2(acc[mi][2 * ph + 1], l1, h1);
            float4 r;
            r.x = (l0 + bl.x >= 1.0f) ? 1.0f : 0.0f;
            r.y = (h0 + bl.y >= 1.0f) ? 1.0f : 0.0f;
            r.z = (l1 + bl.z >= 1.0f) ? 1.0f : 0.0f;
            r.w = (h1 + bl.w >= 1.0f) ? 1.0f : 0.0f;
            *(float4*)&out[(size_t)m * DD + n0 + nl] = r;
        }
    }
}

// ---------------- launch ----------------
extern "C" void kernel_launch(void* const* d_in, const int* in_sizes, int n_in,
                              void* d_out, int out_size)
{
    const float* query = (const float*)d_in[0];
    const float* key   = (const float*)d_in[1];
    const float* value = (const float*)d_in[2];
    const float* scale = (const float*)d_in[3];
    const float* Wq = (const float*)d_in[4];  const float* bq = (const float*)d_in[5];
    const float* Wk = (const float*)d_in[6];  const float* bk = (const float*)d_in[7];
    const float* Wv = (const float*)d_in[8];  const float* bv = (const float*)d_in[9];
    const float* Wo = (const float*)d_in[10]; const float* bo = (const float*)d_in[11];
    float* out = (float*)d_out;

    const int DIN = in_sizes[0] / MROWS;   // 100

    qkv_proj_kernel<<<768, 256>>>(query, key, value, Wq, Wk, Wv, bq, bk, bv, DIN);
    vtrans_kernel<<<BHN * (TT / 64), 64>>>();
    attn_kernel<<<BHN * (TT / 64), 128>>>(scale);
    out_proj_kernel<<<dim3(4, 64), 256>>>(Wo, bo, out);
}